// round 5
// baseline (speedup 1.0000x reference)
#include <cuda_runtime.h>
#include <cstdint>

// Problem shape (fixed by the dataset): B=4, S=2048, D=4096
#define DDIM   4096
#define M_ROWS 8192
#define N_ROWS 4096

// ---------------- scratch (__device__ globals, allocation-free) ----------------
__device__ __align__(256) int8_t g_qx[(size_t)M_ROWS * DDIM];   // quantized x
__device__ __align__(256) int8_t g_qw[(size_t)N_ROWS * DDIM];   // quantized w
__device__ float g_sa[M_ROWS];   // ax/127 per token row
__device__ float g_sw[N_ROWS];   // aw/127 per output row

// ---------------- PTX helpers ----------------
__device__ __forceinline__ uint32_t smem_u32(const void* p) {
    uint32_t a;
    asm("{ .reg .u64 t; cvta.to.shared.u64 t, %1; cvt.u32.u64 %0, t; }" : "=r"(a) : "l"(p));
    return a;
}
__device__ __forceinline__ void cp16(uint32_t dst, const void* src) {
    asm volatile("cp.async.cg.shared.global [%0], [%1], 16;" :: "r"(dst), "l"(src) : "memory");
}
#define CP_COMMIT()  asm volatile("cp.async.commit_group;" ::: "memory")
#define CP_WAIT(n)   asm volatile("cp.async.wait_group %0;" :: "n"(n) : "memory")

__device__ __forceinline__ void ldsm4(uint32_t& r0, uint32_t& r1, uint32_t& r2, uint32_t& r3,
                                      uint32_t addr) {
    asm volatile("ldmatrix.sync.aligned.m8n8.x4.shared.b16 {%0,%1,%2,%3}, [%4];"
                 : "=r"(r0), "=r"(r1), "=r"(r2), "=r"(r3) : "r"(addr));
}
__device__ __forceinline__ void imma16832(int* c, const uint32_t* a, const uint32_t* b) {
    asm volatile(
        "mma.sync.aligned.m16n8k32.row.col.s32.s8.s8.s32 "
        "{%0,%1,%2,%3}, {%4,%5,%6,%7}, {%8,%9}, {%0,%1,%2,%3};\n"
        : "+r"(c[0]), "+r"(c[1]), "+r"(c[2]), "+r"(c[3])
        : "r"(a[0]), "r"(a[1]), "r"(a[2]), "r"(a[3]), "r"(b[0]), "r"(b[1]));
}

// ---------------- fused row-wise absmax int8 quantization ----------------
// Blocks 0..8191: x path (t = x*scales). Blocks 8192..12287: w path (t = w/scales).
__global__ __launch_bounds__(256) void quant_fused_kernel(
    const float* __restrict__ x, const float* __restrict__ w,
    const float* __restrict__ scales)
{
    const int b   = blockIdx.x;
    const bool isx = (b < M_ROWS);
    const int row = isx ? b : (b - M_ROWS);
    const int tid = threadIdx.x;
    const float4* src4 = reinterpret_cast<const float4*>(
        (isx ? x : w) + (size_t)row * DDIM);
    const float4* scl4 = reinterpret_cast<const float4*>(scales);

    float v[16];
    float m = 0.f;
    #pragma unroll
    for (int i = 0; i < 4; i++) {
        int g = i * 256 + tid;
        float4 xv = src4[g];
        float4 s  = scl4[g];
        float t0, t1, t2, t3;
        if (isx) { t0 = xv.x * s.x; t1 = xv.y * s.y; t2 = xv.z * s.z; t3 = xv.w * s.w; }
        else     { t0 = xv.x / s.x; t1 = xv.y / s.y; t2 = xv.z / s.z; t3 = xv.w / s.w; }
        v[i*4+0] = t0; v[i*4+1] = t1; v[i*4+2] = t2; v[i*4+3] = t3;
        m = fmaxf(m, fmaxf(fmaxf(fabsf(t0), fabsf(t1)), fmaxf(fabsf(t2), fabsf(t3))));
    }

    __shared__ float red[8];
    #pragma unroll
    for (int o = 16; o > 0; o >>= 1)
        m = fmaxf(m, __shfl_xor_sync(0xffffffffu, m, o));
    if ((tid & 31) == 0) red[tid >> 5] = m;
    __syncthreads();
    if (tid < 32) {
        float t = (tid < 8) ? red[tid] : 0.f;
        #pragma unroll
        for (int o = 4; o > 0; o >>= 1)
            t = fmaxf(t, __shfl_xor_sync(0xffffffffu, t, o));
        if (tid == 0) red[0] = fmaxf(t, 1e-8f);
    }
    __syncthreads();
    const float absmax = red[0];
    const float qs = 127.f / absmax;

    int* qrow = reinterpret_cast<int*>((isx ? g_qx : g_qw) + (size_t)row * DDIM);
    #pragma unroll
    for (int i = 0; i < 4; i++) {
        int g = i * 256 + tid;
        int packed = 0;
        #pragma unroll
        for (int j = 0; j < 4; j++) {
            float t = rintf(v[i*4+j] * qs);
            t = fminf(fmaxf(t, -127.f), 127.f);
            packed |= ((int)t & 0xff) << (8 * j);
        }
        qrow[g] = packed;
    }
    if (tid == 0) {
        if (isx) g_sa[row] = absmax * (1.f / 127.f);
        else     g_sw[row] = absmax * (1.f / 127.f);
    }
}

// ---------------- pipelined IMMA GEMM: CTA 128x256, BK=128B, 3-stage cp.async ----------------
#define BM      128
#define BN      256
#define BKB     128                          // K bytes per stage
#define NK      (DDIM / BKB)                 // 32
#define A_STAGE (BM * BKB)                   // 16384
#define B_STAGE (BN * BKB)                   // 32768
#define STAGE   (A_STAGE + B_STAGE)          // 49152
#define SMEM_TOTAL (3 * STAGE)               // 147456

__global__ __launch_bounds__(512, 1) void gemm_imma_pipe_kernel(
    const float* __restrict__ bias, const float* __restrict__ scales,
    float* __restrict__ out)
{
    extern __shared__ char smem[];
    const uint32_t sb = smem_u32(smem);
    const int tid  = threadIdx.x;
    const int wid  = tid >> 5;
    const int lane = tid & 31;
    const int wm   = wid >> 2;      // 0..3 (m)
    const int wn   = wid & 3;       // 0..3 (n)
    const int m0   = blockIdx.y * BM;
    const int n0   = blockIdx.x * BN;

    // ---- per-lane ldmatrix base addresses (swizzle: chunk-col ^= row&7) ----
    // A tiles: mt in {0,1}, 16 rows each; matrices (row+0/8, k-lo/hi)
    uint32_t baseA[2]; int rqA[2];
    const int chA = lane >> 4;                    // k-half select
    #pragma unroll
    for (int mt = 0; mt < 2; mt++) {
        int r = wm * 32 + mt * 16 + (lane & 7) + ((lane >> 3) & 1) * 8;
        baseA[mt] = r * BKB;
        rqA[mt]   = r & 7;
    }
    // B loads: p in 0..3, covers n-groups 2p,2p+1; matrices (ngrp 2p k-lo, 2p k-hi, 2p+1 k-lo, 2p+1 k-hi)
    uint32_t baseB[4]; int rqB[4];
    const int chB = (lane >> 3) & 1;
    #pragma unroll
    for (int p = 0; p < 4; p++) {
        int r = wn * 64 + p * 16 + ((lane >> 4) & 1) * 8 + (lane & 7);
        baseB[p] = r * BKB;
        rqB[p]   = r & 7;
    }

    int acc[2][8][4];
    #pragma unroll
    for (int i = 0; i < 2; i++)
        #pragma unroll
        for (int j = 0; j < 8; j++)
            #pragma unroll
            for (int c = 0; c < 4; c++) acc[i][j][c] = 0;

    // ---- stage loader: 6 cp.async(16B) per thread ----
    auto load_stage = [&](int i) {
        const int s = i % 3;
        const int kk = i * BKB;
        const uint32_t sA = sb + s * STAGE;
        const uint32_t sB = sA + A_STAGE;
        #pragma unroll
        for (int j = 0; j < 2; j++) {
            int idx = j * 512 + tid;             // 0..1023
            int r = idx >> 3, c = idx & 7;
            cp16(sA + r * BKB + (((c ^ (r & 7))) << 4),
                 g_qx + (size_t)(m0 + r) * DDIM + kk + c * 16);
        }
        #pragma unroll
        for (int j = 0; j < 4; j++) {
            int idx = j * 512 + tid;             // 0..2047
            int r = idx >> 3, c = idx & 7;
            cp16(sB + r * BKB + (((c ^ (r & 7))) << 4),
                 g_qw + (size_t)(n0 + r) * DDIM + kk + c * 16);
        }
    };

    // prologue: stages 0 and 1 in flight
    load_stage(0); CP_COMMIT();
    load_stage(1); CP_COMMIT();

    for (int i = 0; i < NK; i++) {
        CP_WAIT(1);                 // stage i resident (2 groups outstanding -> oldest done)
        __syncthreads();            // visible to all threads; also protects buffer reuse

        if (i + 2 < NK) load_stage(i + 2);
        CP_COMMIT();                // always commit (empty groups keep count consistent)

        const int s = i % 3;
        const uint32_t sA = sb + s * STAGE;
        const uint32_t sB = sA + A_STAGE;
        #pragma unroll
        for (int ks = 0; ks < 4; ks++) {        // 4 x k32 per 128B stage
            uint32_t a[2][4], b[8][2];
            #pragma unroll
            for (int mt = 0; mt < 2; mt++)
                ldsm4(a[mt][0], a[mt][1], a[mt][2], a[mt][3],
                      sA + baseA[mt] + (((2 * ks + chA) ^ rqA[mt]) << 4));
            #pragma unroll
            for (int p = 0; p < 4; p++)
                ldsm4(b[2*p][0], b[2*p][1], b[2*p+1][0], b[2*p+1][1],
                      sB + baseB[p] + (((2 * ks + chB) ^ rqB[p]) << 4));
            #pragma unroll
            for (int mt = 0; mt < 2; mt++)
                #pragma unroll
                for (int nt = 0; nt < 8; nt++)
                    imma16832(acc[mt][nt], a[mt], b[nt]);
        }
    }

    // ---- epilogue: out = acc * sa[m]*sw[n] + bias[n]/scales[n] ----
    const int g   = lane >> 2;
    const int tig = lane & 3;
    float fw[8][2], fb[8][2];
    #pragma unroll
    for (int nt = 0; nt < 8; nt++) {
        int n = n0 + wn * 64 + nt * 8 + 2 * tig;
        fw[nt][0] = g_sw[n];
        fw[nt][1] = g_sw[n + 1];
        fb[nt][0] = __ldg(&bias[n])     / __ldg(&scales[n]);
        fb[nt][1] = __ldg(&bias[n + 1]) / __ldg(&scales[n + 1]);
    }
    #pragma unroll
    for (int mt = 0; mt < 2; mt++) {
        int mA = m0 + wm * 32 + mt * 16 + g;
        float saA = g_sa[mA];
        float saB = g_sa[mA + 8];
        #pragma unroll
        for (int nt = 0; nt < 8; nt++) {
            int n = n0 + wn * 64 + nt * 8 + 2 * tig;
            float2 o0, o1;
            o0.x = acc[mt][nt][0] * saA * fw[nt][0] + fb[nt][0];
            o0.y = acc[mt][nt][1] * saA * fw[nt][1] + fb[nt][1];
            o1.x = acc[mt][nt][2] * saB * fw[nt][0] + fb[nt][0];
            o1.y = acc[mt][nt][3] * saB * fw[nt][1] + fb[nt][1];
            *reinterpret_cast<float2*>(out + (size_t)mA       * N_ROWS + n) = o0;
            *reinterpret_cast<float2*>(out + (size_t)(mA + 8) * N_ROWS + n) = o1;
        }
    }
}

// ---------------- launch ----------------
extern "C" void kernel_launch(void* const* d_in, const int* in_sizes, int n_in,
                              void* d_out, int out_size)
{
    const float* x      = (const float*)d_in[0];   // [4,2048,4096]
    const float* weight = (const float*)d_in[1];   // [4096,4096]
    const float* bias   = (const float*)d_in[2];   // [4096]
    const float* scales = (const float*)d_in[3];   // [4096]
    float* out = (float*)d_out;                    // [4,2048,4096]

    cudaFuncSetAttribute(gemm_imma_pipe_kernel,
                         cudaFuncAttributeMaxDynamicSharedMemorySize, SMEM_TOTAL);

    quant_fused_kernel<<<M_ROWS + N_ROWS, 256>>>(x, weight, scales);

    dim3 grid(N_ROWS / BN, M_ROWS / BM);   // (16, 64)
    gemm_imma_pipe_kernel<<<grid, 512, SMEM_TOTAL>>>(bias, scales, out);
}

// round 6
// speedup vs baseline: 2.2359x; 2.2359x over previous
#include <cuda_runtime.h>
#include <cstdint>

// Problem shape (fixed by the dataset): B=4, S=2048, D=4096
#define DDIM   4096
#define M_ROWS 8192
#define N_ROWS 4096
#define KINT   (DDIM / 4)          // 1024 ints per row

// ---------------- scratch (__device__ globals, allocation-free) ----------------
__device__ __align__(256) int8_t g_qx[(size_t)M_ROWS * DDIM];   // quantized x
__device__ __align__(256) int8_t g_qw[(size_t)N_ROWS * DDIM];   // quantized w
__device__ float g_sa[M_ROWS];   // ax/127 per token row
__device__ float g_sw[N_ROWS];   // aw/127 per output row

// ---------------- PTX helpers ----------------
__device__ __forceinline__ uint32_t smem_u32(const void* p) {
    uint32_t a;
    asm("{ .reg .u64 t; cvta.to.shared.u64 t, %1; cvt.u32.u64 %0, t; }" : "=r"(a) : "l"(p));
    return a;
}
__device__ __forceinline__ void cp4(uint32_t dst, const void* src) {
    asm volatile("cp.async.ca.shared.global [%0], [%1], 4;" :: "r"(dst), "l"(src) : "memory");
}
#define CP_COMMIT()  asm volatile("cp.async.commit_group;" ::: "memory")
#define CP_WAIT(n)   asm volatile("cp.async.wait_group %0;" :: "n"(n) : "memory")

__device__ __forceinline__ void imma16832(int* c, const uint32_t* a, const uint32_t* b) {
    asm volatile(
        "mma.sync.aligned.m16n8k32.row.col.s32.s8.s8.s32 "
        "{%0,%1,%2,%3}, {%4,%5,%6,%7}, {%8,%9}, {%0,%1,%2,%3};\n"
        : "+r"(c[0]), "+r"(c[1]), "+r"(c[2]), "+r"(c[3])
        : "r"(a[0]), "r"(a[1]), "r"(a[2]), "r"(a[3]), "r"(b[0]), "r"(b[1]));
}

// ---------------- fused row-wise absmax int8 quantization ----------------
// Blocks 0..8191: x path (t = x*scales). Blocks 8192..12287: w path (t = w/scales).
__global__ __launch_bounds__(256) void quant_fused_kernel(
    const float* __restrict__ x, const float* __restrict__ w,
    const float* __restrict__ scales)
{
    const int b    = blockIdx.x;
    const bool isx = (b < M_ROWS);
    const int row  = isx ? b : (b - M_ROWS);
    const int tid  = threadIdx.x;
    const float4* src4 = reinterpret_cast<const float4*>((isx ? x : w) + (size_t)row * DDIM);
    const float4* scl4 = reinterpret_cast<const float4*>(scales);

    float v[16];
    float m = 0.f;
    #pragma unroll
    for (int i = 0; i < 4; i++) {
        int g = i * 256 + tid;
        float4 xv = src4[g];
        float4 s  = scl4[g];
        float t0, t1, t2, t3;
        if (isx) { t0 = xv.x * s.x; t1 = xv.y * s.y; t2 = xv.z * s.z; t3 = xv.w * s.w; }
        else     { t0 = xv.x / s.x; t1 = xv.y / s.y; t2 = xv.z / s.z; t3 = xv.w / s.w; }
        v[i*4+0] = t0; v[i*4+1] = t1; v[i*4+2] = t2; v[i*4+3] = t3;
        m = fmaxf(m, fmaxf(fmaxf(fabsf(t0), fabsf(t1)), fmaxf(fabsf(t2), fabsf(t3))));
    }

    __shared__ float red[8];
    #pragma unroll
    for (int o = 16; o > 0; o >>= 1)
        m = fmaxf(m, __shfl_xor_sync(0xffffffffu, m, o));
    if ((tid & 31) == 0) red[tid >> 5] = m;
    __syncthreads();
    if (tid < 32) {
        float t = (tid < 8) ? red[tid] : 0.f;
        #pragma unroll
        for (int o = 4; o > 0; o >>= 1)
            t = fmaxf(t, __shfl_xor_sync(0xffffffffu, t, o));
        if (tid == 0) red[0] = fmaxf(t, 1e-8f);
    }
    __syncthreads();
    const float absmax = red[0];
    const float qs = 127.f / absmax;

    int* qrow = reinterpret_cast<int*>((isx ? g_qx : g_qw) + (size_t)row * DDIM);
    #pragma unroll
    for (int i = 0; i < 4; i++) {
        int g = i * 256 + tid;
        int packed = 0;
        #pragma unroll
        for (int j = 0; j < 4; j++) {
            float t = rintf(v[i*4+j] * qs);
            t = fminf(fmaxf(t, -127.f), 127.f);
            packed |= ((int)t & 0xff) << (8 * j);
        }
        qrow[g] = packed;
    }
    if (tid == 0) {
        if (isx) g_sa[row] = absmax * (1.f / 127.f);
        else     g_sw[row] = absmax * (1.f / 127.f);
    }
}

// ---------------- hybrid GEMM: dp4a warps (n 0-63) + IMMA warps (n 64-127) ----------------
// CTA tile 128x128, K-chunk = 16 ints (64 int8). Transposed smem tiles [ki][row],
// row stride 136 ints: dp4a gets contiguous int4 rows; IMMA scalar loads hit
// bank (8*ki + r) % 32 -> conflict-free permutations for both fragment patterns.
#define NCHUNK (KINT / 16)       // 64
#define TSTR   136               // ints per smem row (128 + 8 pad)

__global__ __launch_bounds__(256, 2) void gemm_hybrid_kernel(
    const float* __restrict__ bias, const float* __restrict__ scales,
    float* __restrict__ out)
{
    __shared__ int As[2][16][TSTR];
    __shared__ int Bs[2][16][TSTR];

    const int tid  = threadIdx.x;
    const int wid  = tid >> 5;
    const int lane = tid & 31;
    const int m0   = blockIdx.y * 128;
    const int n0   = blockIdx.x * 128;

    const int* qxi = reinterpret_cast<const int*>(g_qx);
    const int* qwi = reinterpret_cast<const int*>(g_qw);
    const uint32_t aBase = smem_u32(&As[0][0][0]);
    const uint32_t bBase = smem_u32(&Bs[0][0][0]);

    // stage loader: all 256 threads; 8 x 4B cp.async per matrix per thread.
    // tid -> (m = idx>>4, ki = idx&15): global reads 64B-coalesced per row pair.
    auto load_stage = [&](int c) {
        const int s = c & 1;
        const uint32_t sOff = (uint32_t)s * (16 * TSTR * 4);
        #pragma unroll
        for (int j = 0; j < 8; j++) {
            int idx = j * 256 + tid;          // 0..2047
            int m = idx >> 4, ki = idx & 15;
            uint32_t d = (uint32_t)(ki * TSTR + m) * 4 + sOff;
            cp4(aBase + d, qxi + (size_t)(m0 + m) * KINT + c * 16 + ki);
            cp4(bBase + d, qwi + (size_t)(n0 + m) * KINT + c * 16 + ki);
        }
    };

    if (wid < 4) {
        // ================= dp4a half: n in [0,64) =================
        const int ty = tid >> 3;      // 0..15 (m)
        const int tx = tid & 7;       // 0..7  (n)
        int acc[8][8];
        #pragma unroll
        for (int i = 0; i < 8; i++)
            #pragma unroll
            for (int j = 0; j < 8; j++) acc[i][j] = 0;

        load_stage(0); CP_COMMIT();
        for (int c = 0; c < NCHUNK; c++) {
            if (c + 1 < NCHUNK) { load_stage(c + 1); CP_COMMIT(); CP_WAIT(1); }
            else                { CP_WAIT(0); }
            __syncthreads();
            const int s = c & 1;
            #pragma unroll
            for (int ki = 0; ki < 16; ki++) {
                int a[8], b[8];
                *reinterpret_cast<int4*>(&a[0]) = *reinterpret_cast<const int4*>(&As[s][ki][ty * 8]);
                *reinterpret_cast<int4*>(&a[4]) = *reinterpret_cast<const int4*>(&As[s][ki][ty * 8 + 4]);
                *reinterpret_cast<int4*>(&b[0]) = *reinterpret_cast<const int4*>(&Bs[s][ki][tx * 8]);
                *reinterpret_cast<int4*>(&b[4]) = *reinterpret_cast<const int4*>(&Bs[s][ki][tx * 8 + 4]);
                #pragma unroll
                for (int i = 0; i < 8; i++)
                    #pragma unroll
                    for (int j = 0; j < 8; j++)
                        acc[i][j] = __dp4a(a[i], b[j], acc[i][j]);
            }
            __syncthreads();
        }

        // epilogue
        float fw[8], fb[8];
        #pragma unroll
        for (int j = 0; j < 8; j++) {
            int n = n0 + tx * 8 + j;
            fw[j] = g_sw[n];
            fb[j] = __ldg(&bias[n]) / __ldg(&scales[n]);
        }
        #pragma unroll
        for (int i = 0; i < 8; i++) {
            int m = m0 + ty * 8 + i;
            float fa = g_sa[m];
            float4 o0, o1;
            o0.x = acc[i][0]*fa*fw[0]+fb[0]; o0.y = acc[i][1]*fa*fw[1]+fb[1];
            o0.z = acc[i][2]*fa*fw[2]+fb[2]; o0.w = acc[i][3]*fa*fw[3]+fb[3];
            o1.x = acc[i][4]*fa*fw[4]+fb[4]; o1.y = acc[i][5]*fa*fw[5]+fb[5];
            o1.z = acc[i][6]*fa*fw[6]+fb[6]; o1.w = acc[i][7]*fa*fw[7]+fb[7];
            float4* orow = reinterpret_cast<float4*>(out + (size_t)m * N_ROWS + n0 + tx * 8);
            orow[0] = o0; orow[1] = o1;
        }
    } else {
        // ================= IMMA half: n in [64,128) =================
        const int wi  = wid - 4;        // 0..3
        const int wm  = wi >> 1;        // m-offset wm*64
        const int wn  = wi & 1;         // n-offset 64 + wn*32
        const int g   = lane >> 2;
        const int tig = lane & 3;
        int acc[4][4][4];
        #pragma unroll
        for (int i = 0; i < 4; i++)
            #pragma unroll
            for (int j = 0; j < 4; j++)
                #pragma unroll
                for (int k = 0; k < 4; k++) acc[i][j][k] = 0;

        load_stage(0); CP_COMMIT();
        for (int c = 0; c < NCHUNK; c++) {
            if (c + 1 < NCHUNK) { load_stage(c + 1); CP_COMMIT(); CP_WAIT(1); }
            else                { CP_WAIT(0); }
            __syncthreads();
            const int s = c & 1;
            #pragma unroll
            for (int ks = 0; ks < 2; ks++) {
                const int klo = ks * 8 + tig, khi = klo + 4;
                uint32_t a[4][4], b[4][2];
                #pragma unroll
                for (int mt = 0; mt < 4; mt++) {
                    int r = wm * 64 + mt * 16 + g;
                    a[mt][0] = (uint32_t)As[s][klo][r];
                    a[mt][1] = (uint32_t)As[s][klo][r + 8];
                    a[mt][2] = (uint32_t)As[s][khi][r];
                    a[mt][3] = (uint32_t)As[s][khi][r + 8];
                }
                #pragma unroll
                for (int nt = 0; nt < 4; nt++) {
                    int n = 64 + wn * 32 + nt * 8 + g;
                    b[nt][0] = (uint32_t)Bs[s][klo][n];
                    b[nt][1] = (uint32_t)Bs[s][khi][n];
                }
                #pragma unroll
                for (int mt = 0; mt < 4; mt++)
                    #pragma unroll
                    for (int nt = 0; nt < 4; nt++)
                        imma16832(acc[mt][nt], a[mt], b[nt]);
            }
            __syncthreads();
        }

        // epilogue (C frag: c0 (g,2tig), c1 (g,2tig+1), c2 (g+8,2tig), c3 (g+8,2tig+1))
        float fw[4][2], fb[4][2];
        #pragma unroll
        for (int nt = 0; nt < 4; nt++) {
            int n = n0 + 64 + wn * 32 + nt * 8 + 2 * tig;
            fw[nt][0] = g_sw[n];
            fw[nt][1] = g_sw[n + 1];
            fb[nt][0] = __ldg(&bias[n])     / __ldg(&scales[n]);
            fb[nt][1] = __ldg(&bias[n + 1]) / __ldg(&scales[n + 1]);
        }
        #pragma unroll
        for (int mt = 0; mt < 4; mt++) {
            int mA = m0 + wm * 64 + mt * 16 + g;
            float saA = g_sa[mA];
            float saB = g_sa[mA + 8];
            #pragma unroll
            for (int nt = 0; nt < 4; nt++) {
                int n = n0 + 64 + wn * 32 + nt * 8 + 2 * tig;
                float2 o0, o1;
                o0.x = acc[mt][nt][0] * saA * fw[nt][0] + fb[nt][0];
                o0.y = acc[mt][nt][1] * saA * fw[nt][1] + fb[nt][1];
                o1.x = acc[mt][nt][2] * saB * fw[nt][0] + fb[nt][0];
                o1.y = acc[mt][nt][3] * saB * fw[nt][1] + fb[nt][1];
                *reinterpret_cast<float2*>(out + (size_t)mA       * N_ROWS + n) = o0;
                *reinterpret_cast<float2*>(out + (size_t)(mA + 8) * N_ROWS + n) = o1;
            }
        }
    }
}

// ---------------- launch ----------------
extern "C" void kernel_launch(void* const* d_in, const int* in_sizes, int n_in,
                              void* d_out, int out_size)
{
    const float* x      = (const float*)d_in[0];   // [4,2048,4096]
    const float* weight = (const float*)d_in[1];   // [4096,4096]
    const float* bias   = (const float*)d_in[2];   // [4096]
    const float* scales = (const float*)d_in[3];   // [4096]
    float* out = (float*)d_out;                    // [4,2048,4096]

    quant_fused_kernel<<<M_ROWS + N_ROWS, 256>>>(x, weight, scales);

    dim3 grid(N_ROWS / 128, M_ROWS / 128);   // (32, 64)
    gemm_hybrid_kernel<<<grid, 256>>>(bias, scales, out);
}